// round 11
// baseline (speedup 1.0000x reference)
#include <cuda_runtime.h>

typedef unsigned long long u64;

#define KK    81
#define MM    16
#define JJ    8
#define CINN  64
#define COUTN 64
#define HH    64
#define WW    64
#define NB    32
#define TLW   16
#define TLH   16
#define XROWS (TLH + 8)           /* 24 */
#define XCOLS (TLW + 8)           /* 24 */
#define XPIX  (XROWS * XCOLS)     /* 576 */
#define NCP   (CINN / 2)          /* 32 cin pairs */
#define NCQ   (CINN / 4)          /* 16 4-cin blocks */
#define NPIX  256
#define NTHREADS 512
#define SM_XF2  (NCP * XPIX)       /* 18432 float2 = 147456 B */
#define SM_TSN  (KK * JJ)          /* 648 u64 = 5184 B */
#define SM_WSF  4096               /* 16384 B : [64 seg][64 cout] */
#define SM_USN  (2 * JJ * NPIX)    /* 4096 u64 = 32768 B : [2 cin][8 j][256 pix] */
#define SMEM_BYTES (SM_XF2 * 8 + SM_TSN * 8 + SM_WSF * 4 + SM_USN * 8) /* 201792 */

// ---- packed fp32x2 helpers (sm_103a) ----
__device__ __forceinline__ u64 ffma2(u64 a, u64 b, u64 c) {
    u64 d;
    asm("fma.rn.f32x2 %0, %1, %2, %3;" : "=l"(d) : "l"(a), "l"(b), "l"(c));
    return d;
}
__device__ __forceinline__ u64 pack2(float lo, float hi) {
    u64 d;
    asm("mov.b64 %0, {%1, %2};" : "=l"(d) : "f"(lo), "f"(hi));
    return d;
}
__device__ __forceinline__ float2 unpack2(u64 d) {
    float2 r;
    asm("mov.b64 {%0, %1}, %2;" : "=f"(r.x), "=f"(r.y) : "l"(d));
    return r;
}

extern __shared__ float smem_raw[];

__global__ void __launch_bounds__(NTHREADS, 1)
bessel_conv_kernel(const float* __restrict__ x,
                   const float* __restrict__ T_real,
                   const float* __restrict__ T_imag,
                   const float* __restrict__ w_r,
                   const float* __restrict__ w_i,
                   const float* __restrict__ bias,
                   float* __restrict__ out)
{
    float2* xs2 = (float2*)smem_raw;                 // [NCP][24][24]
    u64*    Ts  = (u64*)(smem_raw + SM_XF2 * 2);     // [81][8] packed (Tr,Ti)
    float*  ws  = (float*)(Ts + SM_TSN);             // [64 seg][64 cout]
    u64*    us  = (u64*)(ws + SM_WSF);               // [2 cin][8 j][256 pix]

    const int tid = threadIdx.x;
    const int hf  = tid >> 8;              // 0/1 : j-half (StageA) & cout-half (StageB)
    const int p   = tid & 255;             // pixel id in tile
    const int tx  = p & 15;
    const int ty  = p >> 4;
    const int tileX = blockIdx.x;          // 0..3
    const int tileY = blockIdx.y;          // 0..3
    const int b     = blockIdx.z;          // 0..31

    const int gx = tileX * TLW + tx;
    const int gy = tileY * TLH + ty;

    // ---- w staging role: seg = (ri,jj,c) of 64, 8 threads/seg, 8 couts each ----
    const int seg   = tid >> 3;            // 0..63
    const int lane8 = tid & 7;             // 0..7
    const int w_ri  = seg >> 5;            // 0 = real, 1 = imag
    const int w_jj  = (seg >> 2) & 7;
    const int w_c   = seg & 3;
    float* ws_dst = ws + seg * 64 + lane8 * 8;
    const float* wbase0 = w_ri ? w_i : w_r;

    // ---------- stage x tile (+4 halo, zero padded), cin-paired float2 ----------
    {
        const int baseY = tileY * TLH - 4;
        const int baseX = tileX * TLW - 4;
        const float* xb = x + (size_t)b * CINN * HH * WW;
        for (int idx = tid; idx < SM_XF2; idx += NTHREADS) {
            int cp  = idx / XPIX;
            int rem = idx - cp * XPIX;
            int r   = rem / XCOLS;
            int c   = rem - r * XCOLS;
            int iy  = baseY + r;
            int ix  = baseX + c;
            float2 v = make_float2(0.0f, 0.0f);
            if (iy >= 0 && iy < HH && ix >= 0 && ix < WW) {
                const float* pb = xb + ((size_t)(2 * cp) * HH + iy) * WW + ix;
                v.x = pb[0];
                v.y = pb[(size_t)HH * WW];
            }
            xs2[idx] = v;
        }
    }

    const int pixoff = ty * XCOLS + tx;   // this thread's pixel base
    float* ob = out + ((size_t)b * COUTN + hf * 32) * (HH * WW) + gy * WW + gx;

#pragma unroll 1
    for (int m = 0; m < MM; ++m) {
        __syncthreads();   // previous m's readers of Ts done (and x at m=0)
        // ---- stage T[m] as packed (Tr,Ti) pairs: Ts[k*8+j] ----
        for (int idx = tid; idx < SM_TSN; idx += NTHREADS) {
            Ts[idx] = pack2(T_real[m * SM_TSN + idx],
                            T_imag[m * SM_TSN + idx]);
        }

        // this thread's w source for cq=0 (advances 256 floats per cq)
        const float* w_src = wbase0
                           + (((size_t)m * JJ + w_jj) * CINN + w_c) * COUTN
                           + lane8 * 8;

        u64 yr[16], yi[16];   // 32 couts (this half), packed 2-wide
#pragma unroll
        for (int t = 0; t < 16; ++t) { yr[t] = 0ULL; yi[t] = 0ULL; }

#pragma unroll 1
        for (int cq = 0; cq < NCQ; ++cq) {
            // ---- Stage A: u[4 cins][4 js of my j-half] for my pixel ----
            u64 u[4][4];
#pragma unroll
            for (int c = 0; c < 4; ++c)
#pragma unroll
                for (int jl = 0; jl < 4; ++jl) u[c][jl] = 0ULL;

            const float2* xp0 = xs2 + (2 * cq) * XPIX + pixoff;
            const float2* xp1 = xp0 + XPIX;
            const ulonglong2* tsh = (const ulonglong2*)(Ts + hf * 4);

#pragma unroll 3
            for (int k1 = 0; k1 < 9; ++k1) {
#pragma unroll
                for (int k2 = 0; k2 < 9; ++k2) {
                    const int k = k1 * 9 + k2;
                    ulonglong2 t0 = tsh[k * 4];       // j = hf*4 + {0,1}
                    ulonglong2 t1 = tsh[k * 4 + 1];   // j = hf*4 + {2,3}
                    float2 xv01 = xp0[k1 * XCOLS + k2];
                    float2 xv23 = xp1[k1 * XCOLS + k2];
                    u64 xd0 = pack2(xv01.x, xv01.x);
                    u64 xd1 = pack2(xv01.y, xv01.y);
                    u64 xd2 = pack2(xv23.x, xv23.x);
                    u64 xd3 = pack2(xv23.y, xv23.y);
                    u[0][0] = ffma2(t0.x, xd0, u[0][0]);
                    u[0][1] = ffma2(t0.y, xd0, u[0][1]);
                    u[0][2] = ffma2(t1.x, xd0, u[0][2]);
                    u[0][3] = ffma2(t1.y, xd0, u[0][3]);
                    u[1][0] = ffma2(t0.x, xd1, u[1][0]);
                    u[1][1] = ffma2(t0.y, xd1, u[1][1]);
                    u[1][2] = ffma2(t1.x, xd1, u[1][2]);
                    u[1][3] = ffma2(t1.y, xd1, u[1][3]);
                    u[2][0] = ffma2(t0.x, xd2, u[2][0]);
                    u[2][1] = ffma2(t0.y, xd2, u[2][1]);
                    u[2][2] = ffma2(t1.x, xd2, u[2][2]);
                    u[2][3] = ffma2(t1.y, xd2, u[2][3]);
                    u[3][0] = ffma2(t0.x, xd3, u[3][0]);
                    u[3][1] = ffma2(t0.y, xd3, u[3][1]);
                    u[3][2] = ffma2(t1.x, xd3, u[3][2]);
                    u[3][3] = ffma2(t1.y, xd3, u[3][3]);
                }
            }

            // ---- load w slice for this cq (short live range) ----
            float4 wv0, wv1;
            {
                const float4* s = (const float4*)(w_src + (size_t)cq * 4 * COUTN);
                wv0 = __ldg(s);
                wv1 = __ldg(s + 1);
            }

            __syncthreads();   // prior phase-2 readers of ws/us done
            ((float4*)ws_dst)[0] = wv0;
            ((float4*)ws_dst)[1] = wv1;
            // phase-1 u: cins {0,1} of this block, my j's
#pragma unroll
            for (int c = 0; c < 2; ++c)
#pragma unroll
                for (int jl = 0; jl < 4; ++jl)
                    us[(c * JJ + hf * 4 + jl) * NPIX + p] = u[c][jl];
            __syncthreads();   // ws + us(01) visible

            // ---- Stage B phase 1: cins {0,1}, my 32 couts ----
#pragma unroll
            for (int c = 0; c < 2; ++c) {
#pragma unroll
                for (int jj = 0; jj < 8; ++jj) {
                    float2 uv = unpack2(us[(c * JJ + jj) * NPIX + p]);
                    u64 ur2  = pack2(uv.x, uv.x);
                    u64 ui2  = pack2(uv.y, uv.y);
                    u64 nui2 = pack2(-uv.y, -uv.y);
                    const ulonglong2* wrw =
                        (const ulonglong2*)(ws + (jj * 4 + c) * 64 + hf * 32);
                    const ulonglong2* wiw =
                        (const ulonglong2*)(ws + (32 + jj * 4 + c) * 64 + hf * 32);
#pragma unroll
                    for (int q = 0; q < 8; ++q) {
                        ulonglong2 a  = wrw[q];
                        ulonglong2 bb = wiw[q];
                        yr[2*q]   = ffma2(ur2,  a.x,  yr[2*q]);
                        yr[2*q]   = ffma2(nui2, bb.x, yr[2*q]);
                        yi[2*q]   = ffma2(ur2,  bb.x, yi[2*q]);
                        yi[2*q]   = ffma2(ui2,  a.x,  yi[2*q]);
                        yr[2*q+1] = ffma2(ur2,  a.y,  yr[2*q+1]);
                        yr[2*q+1] = ffma2(nui2, bb.y, yr[2*q+1]);
                        yi[2*q+1] = ffma2(ur2,  bb.y, yi[2*q+1]);
                        yi[2*q+1] = ffma2(ui2,  a.y,  yi[2*q+1]);
                    }
                }
            }

            __syncthreads();   // phase-1 reads of us done
            // phase-2 u: cins {2,3}
#pragma unroll
            for (int c = 0; c < 2; ++c)
#pragma unroll
                for (int jl = 0; jl < 4; ++jl)
                    us[(c * JJ + hf * 4 + jl) * NPIX + p] = u[2 + c][jl];
            __syncthreads();   // us(23) visible

            // ---- Stage B phase 2: cins {2,3}, my 32 couts ----
#pragma unroll
            for (int c = 0; c < 2; ++c) {
#pragma unroll
                for (int jj = 0; jj < 8; ++jj) {
                    float2 uv = unpack2(us[(c * JJ + jj) * NPIX + p]);
                    u64 ur2  = pack2(uv.x, uv.x);
                    u64 ui2  = pack2(uv.y, uv.y);
                    u64 nui2 = pack2(-uv.y, -uv.y);
                    const ulonglong2* wrw =
                        (const ulonglong2*)(ws + (jj * 4 + 2 + c) * 64 + hf * 32);
                    const ulonglong2* wiw =
                        (const ulonglong2*)(ws + (32 + jj * 4 + 2 + c) * 64 + hf * 32);
#pragma unroll
                    for (int q = 0; q < 8; ++q) {
                        ulonglong2 a  = wrw[q];
                        ulonglong2 bb = wiw[q];
                        yr[2*q]   = ffma2(ur2,  a.x,  yr[2*q]);
                        yr[2*q]   = ffma2(nui2, bb.x, yr[2*q]);
                        yi[2*q]   = ffma2(ur2,  bb.x, yi[2*q]);
                        yi[2*q]   = ffma2(ui2,  a.x,  yi[2*q]);
                        yr[2*q+1] = ffma2(ur2,  a.y,  yr[2*q+1]);
                        yr[2*q+1] = ffma2(nui2, bb.y, yr[2*q+1]);
                        yi[2*q+1] = ffma2(ur2,  bb.y, yi[2*q+1]);
                        yi[2*q+1] = ffma2(ui2,  a.y,  yi[2*q+1]);
                    }
                }
            }
        }

        // ---- epilogue: out RMW for my 32 couts. m=0 initializes ----
        if (m == 0) {
#pragma unroll
            for (int t = 0; t < 16; ++t) {
                float2 r  = unpack2(yr[t]);
                float2 im = unpack2(yi[t]);
                ob[(size_t)(2*t)     * (HH*WW)] =
                    r.x * r.x + im.x * im.x + __ldg(bias + hf * 32 + 2*t);
                ob[(size_t)(2*t + 1) * (HH*WW)] =
                    r.y * r.y + im.y * im.y + __ldg(bias + hf * 32 + 2*t + 1);
            }
        } else {
#pragma unroll
            for (int t = 0; t < 16; ++t) {
                float2 r  = unpack2(yr[t]);
                float2 im = unpack2(yi[t]);
                float p0 = ob[(size_t)(2*t)     * (HH*WW)];
                float p1 = ob[(size_t)(2*t + 1) * (HH*WW)];
                ob[(size_t)(2*t)     * (HH*WW)] = p0 + r.x * r.x + im.x * im.x;
                ob[(size_t)(2*t + 1) * (HH*WW)] = p1 + r.y * r.y + im.y * im.y;
            }
        }
    }
}

extern "C" void kernel_launch(void* const* d_in, const int* in_sizes, int n_in,
                              void* d_out, int out_size)
{
    (void)in_sizes; (void)n_in; (void)out_size;
    const float* x  = (const float*)d_in[0];
    const float* Tr = (const float*)d_in[1];
    const float* Ti = (const float*)d_in[2];
    const float* wr = (const float*)d_in[3];
    const float* wi = (const float*)d_in[4];
    const float* b  = (const float*)d_in[5];
    float* out = (float*)d_out;

    cudaFuncSetAttribute(bessel_conv_kernel,
                         cudaFuncAttributeMaxDynamicSharedMemorySize, SMEM_BYTES);

    dim3 grid(WW / TLW, HH / TLH, NB);   // (4, 4, 32) = 512 CTAs
    bessel_conv_kernel<<<grid, NTHREADS, SMEM_BYTES>>>(x, Tr, Ti, wr, wi, b, out);
}

// round 14
// speedup vs baseline: 1.4963x; 1.4963x over previous
#include <cuda_runtime.h>

typedef unsigned long long u64;
typedef unsigned int u32;

#define KK    81
#define MM    16
#define JJ    8
#define CINN  64
#define COUTN 64
#define HH    64
#define WW    64
#define TLW   16
#define TLH   16
#define XCOLS 24
#define XPIX  576
#define NCP   32
#define NTHREADS 256

/* smem layout (bytes) */
#define SM_TS   147456            /* x tile: 32 cp * 576 * 8B           */
#define SM_U    152640            /* Ts: 648 u64 = 5184B                */
#define U_PITCH 36                /* 16 bf16 row + 4B pad (9 words)     */
#define U_VAR   (256 * U_PITCH)   /* 9216B per variant, 4 variants      */
#define SM_W    189504            /* = SM_U + 4*9216                    */
#define W_PITCH 36
#define W_VAR   (64 * W_PITCH)    /* 2304B per variant, 6 variants      */
#define SMEM_BYTES (SM_W + 6 * W_VAR)   /* 203328 */

/* ---- packed fp32x2 helpers (Stage A, verified) ---- */
__device__ __forceinline__ u64 ffma2(u64 a, u64 b, u64 c) {
    u64 d; asm("fma.rn.f32x2 %0, %1, %2, %3;" : "=l"(d) : "l"(a), "l"(b), "l"(c)); return d;
}
__device__ __forceinline__ u64 pack2(float lo, float hi) {
    u64 d; asm("mov.b64 %0, {%1, %2};" : "=l"(d) : "f"(lo), "f"(hi)); return d;
}
__device__ __forceinline__ float2 unpack2(u64 d) {
    float2 r; asm("mov.b64 {%0, %1}, %2;" : "=f"(r.x), "=f"(r.y) : "l"(d)); return r;
}
/* bf16x2 pack: element0 (low 16) = lo, element1 (high 16) = hi */
__device__ __forceinline__ u32 bf2(float lo, float hi) {
    u32 r; asm("cvt.rn.bf16x2.f32 %0, %1, %2;" : "=r"(r) : "f"(hi), "f"(lo)); return r;
}
__device__ __forceinline__ float bflo(u32 w) { return __uint_as_float(w << 16); }
__device__ __forceinline__ float bfhi(u32 w) { return __uint_as_float(w & 0xffff0000u); }

/* mma.sync m16n8k16 bf16 -> f32 accumulate (baseline PTX, valid on sm_103) */
__device__ __forceinline__ void mma16816(float* d, const u32* a, const u32* b) {
    asm("mma.sync.aligned.m16n8k16.row.col.f32.bf16.bf16.f32 "
        "{%0,%1,%2,%3}, {%4,%5,%6,%7}, {%8,%9}, {%0,%1,%2,%3};"
        : "+f"(d[0]), "+f"(d[1]), "+f"(d[2]), "+f"(d[3])
        : "r"(a[0]), "r"(a[1]), "r"(a[2]), "r"(a[3]), "r"(b[0]), "r"(b[1]));
}

extern __shared__ char smem_raw[];

__global__ void __launch_bounds__(NTHREADS, 1)
bessel_conv_kernel(const float* __restrict__ x,
                   const float* __restrict__ T_real,
                   const float* __restrict__ T_imag,
                   const float* __restrict__ w_r,
                   const float* __restrict__ w_i,
                   const float* __restrict__ bias,
                   float* __restrict__ out)
{
    float2* xs2 = (float2*)smem_raw;                 /* [32 cp][576 px] */
    u64*    Ts  = (u64*)(smem_raw + SM_TS);          /* [81][8] packed (Tr,Ti) */

    const int tid  = threadIdx.x;
    const int lane = tid & 31;
    const int wid  = tid >> 5;
    const int tx   = tid & 15, ty = tid >> 4;
    const int tileX = blockIdx.x, tileY = blockIdx.y, b = blockIdx.z;
    const int r4 = lane >> 2, t4 = lane & 3;

    /* W staging role: kpair = wid (0..7) -> k = 2*kpair, 2*kpair+1 */
    const int wc  = wid >> 2;            /* cin within pair           */
    const int wj  = (wid & 3) * 2;       /* j of even k               */
    const int wn2 = lane * 2;            /* 2 couts per thread        */

    /* ---- stage x tile (+4 halo, zero padded), cin-paired float2 ---- */
    {
        const int baseY = tileY * TLH - 4, baseX = tileX * TLW - 4;
        const float* xb = x + (size_t)b * CINN * HH * WW;
        for (int idx = tid; idx < NCP * XPIX; idx += NTHREADS) {
            int cp = idx / XPIX, rem = idx - cp * XPIX;
            int r = rem / XCOLS, c = rem - r * XCOLS;
            int iy = baseY + r, ix = baseX + c;
            float2 v = make_float2(0.f, 0.f);
            if (iy >= 0 && iy < HH && ix >= 0 && ix < WW) {
                const float* pb = xb + ((size_t)(2 * cp) * HH + iy) * WW + ix;
                v.x = pb[0]; v.y = pb[(size_t)HH * WW];
            }
            xs2[idx] = v;
        }
    }

    const int pixoff = ty * XCOLS + tx;

    /* product tables: A variant {0:Urh,1:Url,2:Uih,3:Uil},
       W variant {0:Wrh,1:Wrl,2:Wih,3:Wil,4:-Wih,5:-Wil} */
    const int PA[6]  = {0, 1, 0, 2, 3, 2};
    const int PBR[6] = {0, 0, 1, 4, 4, 5};
    const int PBI[6] = {2, 2, 3, 0, 0, 1};

#pragma unroll 1
    for (int m = 0; m < MM; ++m) {
        __syncthreads();                 /* previous m's smem readers done */
        for (int idx = tid; idx < KK * JJ; idx += NTHREADS)
            Ts[idx] = pack2(T_real[m * KK * JJ + idx], T_imag[m * KK * JJ + idx]);
        __syncthreads();                 /* Ts (and x at m=0) visible */

        float Dk[2][8][2][4];            /* [mtile][ntile][re/im][frag] */
#pragma unroll
        for (int a = 0; a < 2; ++a)
#pragma unroll
            for (int n = 0; n < 8; ++n)
#pragma unroll
                for (int e = 0; e < 2; ++e)
#pragma unroll
                    for (int q = 0; q < 4; ++q) Dk[a][n][e][q] = 0.f;

#pragma unroll 1
        for (int cp = 0; cp < NCP; ++cp) {
            /* ---- W prefetch for this (m,cp): 4x LDG.64, coalesced ---- */
            const float* wrp = w_r + (((size_t)m * JJ + wj) * CINN + (2 * cp + wc)) * COUTN + wn2;
            const float* wip = w_i + (((size_t)m * JJ + wj) * CINN + (2 * cp + wc)) * COUTN + wn2;
            float2 pr0 = __ldg((const float2*)wrp);
            float2 pr1 = __ldg((const float2*)(wrp + CINN * COUTN));
            float2 pi0 = __ldg((const float2*)wip);
            float2 pi1 = __ldg((const float2*)(wip + CINN * COUTN));

            /* ---- Stage A (verified round-8 code): u[2][8] complex ---- */
            u64 u[2][8];
#pragma unroll
            for (int c = 0; c < 2; ++c)
#pragma unroll
                for (int jj = 0; jj < 8; ++jj) u[c][jj] = 0ULL;

            const float2* xp = xs2 + cp * XPIX + pixoff;
#pragma unroll 3
            for (int k1 = 0; k1 < 9; ++k1) {
#pragma unroll
                for (int k2 = 0; k2 < 9; ++k2) {
                    const int k = k1 * 9 + k2;
                    const ulonglong2* tk = (const ulonglong2*)(Ts + k * 8);
                    ulonglong2 t01 = tk[0];
                    ulonglong2 t23 = tk[1];
                    ulonglong2 t45 = tk[2];
                    ulonglong2 t67 = tk[3];
                    float2 xv = xp[k1 * XCOLS + k2];
                    u64 xd0 = pack2(xv.x, xv.x);
                    u64 xd1 = pack2(xv.y, xv.y);
                    u[0][0] = ffma2(t01.x, xd0, u[0][0]);
                    u[0][1] = ffma2(t01.y, xd0, u[0][1]);
                    u[0][2] = ffma2(t23.x, xd0, u[0][2]);
                    u[0][3] = ffma2(t23.y, xd0, u[0][3]);
                    u[0][4] = ffma2(t45.x, xd0, u[0][4]);
                    u[0][5] = ffma2(t45.y, xd0, u[0][5]);
                    u[0][6] = ffma2(t67.x, xd0, u[0][6]);
                    u[0][7] = ffma2(t67.y, xd0, u[0][7]);
                    u[1][0] = ffma2(t01.x, xd1, u[1][0]);
                    u[1][1] = ffma2(t01.y, xd1, u[1][1]);
                    u[1][2] = ffma2(t23.x, xd1, u[1][2]);
                    u[1][3] = ffma2(t23.y, xd1, u[1][3]);
                    u[1][4] = ffma2(t45.x, xd1, u[1][4]);
                    u[1][5] = ffma2(t45.y, xd1, u[1][5]);
                    u[1][6] = ffma2(t67.x, xd1, u[1][6]);
                    u[1][7] = ffma2(t67.y, xd1, u[1][7]);
                }
            }

            __syncthreads();   /* previous GEMM's U/W reads done */

            /* ---- U -> smem bf16 variants; row = pixel(tid), k = 8c+j ---- */
#pragma unroll
            for (int c = 0; c < 2; ++c) {
#pragma unroll
                for (int jp = 0; jp < 4; ++jp) {
                    float2 e0 = unpack2(u[c][2 * jp]);
                    float2 e1 = unpack2(u[c][2 * jp + 1]);
                    u32 rh = bf2(e0.x, e1.x);
                    u32 rl = bf2(e0.x - bflo(rh), e1.x - bfhi(rh));
                    u32 ih = bf2(e0.y, e1.y);
                    u32 il = bf2(e0.y - bflo(ih), e1.y - bfhi(ih));
                    char* ub = smem_raw + SM_U + tid * U_PITCH + (4 * c + jp) * 4;
                    *(u32*)(ub)             = rh;
                    *(u32*)(ub + U_VAR)     = rl;
                    *(u32*)(ub + 2 * U_VAR) = ih;
                    *(u32*)(ub + 3 * U_VAR) = il;
                }
            }

            /* ---- W -> smem bf16 variants; row = cout n, word kpair ---- */
#pragma unroll
            for (int s = 0; s < 2; ++s) {
                float vr0 = s ? pr0.y : pr0.x;   /* k even  */
                float vr1 = s ? pr1.y : pr1.x;   /* k odd   */
                float vi0 = s ? pi0.y : pi0.x;
                float vi1 = s ? pi1.y : pi1.x;
                u32 hR = bf2(vr0, vr1);
                u32 lR = bf2(vr0 - bflo(hR), vr1 - bfhi(hR));
                u32 hI = bf2(vi0, vi1);
                u32 lI = bf2(vi0 - bflo(hI), vi1 - bfhi(hI));
                char* wb = smem_raw + SM_W + (wn2 + s) * W_PITCH + wid * 4;
                *(u32*)(wb)             = hR;
                *(u32*)(wb + W_VAR)     = lR;
                *(u32*)(wb + 2 * W_VAR) = hI;
                *(u32*)(wb + 3 * W_VAR) = lI;
                *(u32*)(wb + 4 * W_VAR) = hI ^ 0x80008000u;
                *(u32*)(wb + 5 * W_VAR) = lI ^ 0x80008000u;
            }
            __syncthreads();   /* U + W visible */

            /* ---- GEMM: warp wid owns rows 32*wid..+31 (2 mtiles) ---- */
            u32 afr[2][4][4];
#pragma unroll
            for (int mt = 0; mt < 2; ++mt) {
                const int row = wid * 32 + mt * 16 + r4;
#pragma unroll
                for (int v = 0; v < 4; ++v) {
                    const char* uv = smem_raw + SM_U + v * U_VAR;
                    afr[mt][v][0] = *(const u32*)(uv + row * U_PITCH + t4 * 4);
                    afr[mt][v][1] = *(const u32*)(uv + (row + 8) * U_PITCH + t4 * 4);
                    afr[mt][v][2] = *(const u32*)(uv + row * U_PITCH + 16 + t4 * 4);
                    afr[mt][v][3] = *(const u32*)(uv + (row + 8) * U_PITCH + 16 + t4 * 4);
                }
            }
#pragma unroll
            for (int nt = 0; nt < 8; ++nt) {
                u32 bfr[6][2];
                const int rowb = nt * 8 + r4;
#pragma unroll
                for (int v = 0; v < 6; ++v) {
                    const char* wv = smem_raw + SM_W + v * W_VAR;
                    bfr[v][0] = *(const u32*)(wv + rowb * W_PITCH + t4 * 4);
                    bfr[v][1] = *(const u32*)(wv + rowb * W_PITCH + 16 + t4 * 4);
                }
#pragma unroll
                for (int mt = 0; mt < 2; ++mt) {
#pragma unroll
                    for (int pi = 0; pi < 6; ++pi)
                        mma16816(Dk[mt][nt][0], afr[mt][PA[pi]], bfr[PBR[pi]]);
#pragma unroll
                    for (int pi = 0; pi < 6; ++pi)
                        mma16816(Dk[mt][nt][1], afr[mt][PA[pi]], bfr[PBI[pi]]);
                }
            }
        }

        /* ---- epilogue: |y|^2 RMW into out (m=0 initializes + bias) ---- */
#pragma unroll
        for (int mt = 0; mt < 2; ++mt) {
#pragma unroll
            for (int nt = 0; nt < 8; ++nt) {
                const float* dR = Dk[mt][nt][0];
                const float* dI = Dk[mt][nt][1];
                const int p0 = wid * 32 + mt * 16 + r4;
                const int p1 = p0 + 8;
                const int c0 = nt * 8 + t4 * 2;
                float v00 = dR[0] * dR[0] + dI[0] * dI[0];
                float v01 = dR[1] * dR[1] + dI[1] * dI[1];
                float v10 = dR[2] * dR[2] + dI[2] * dI[2];
                float v11 = dR[3] * dR[3] + dI[3] * dI[3];
                float* o00 = out + ((size_t)b * COUTN + c0) * (HH * WW)
                           + (tileY * TLH + (p0 >> 4)) * WW + tileX * TLW + (p0 & 15);
                float* o10 = out + ((size_t)b * COUTN + c0) * (HH * WW)
                           + (tileY * TLH + (p1 >> 4)) * WW + tileX * TLW + (p1 & 15);
                if (m == 0) {
                    float b0 = __ldg(bias + c0), b1 = __ldg(bias + c0 + 1);
                    o00[0]       = v00 + b0;
                    o00[HH * WW] = v01 + b1;
                    o10[0]       = v10 + b0;
                    o10[HH * WW] = v11 + b1;
                } else {
                    o00[0]       += v00;
                    o00[HH * WW] += v01;
                    o10[0]       += v10;
                    o10[HH * WW] += v11;
                }
            }
        }
    }
}

extern "C" void kernel_launch(void* const* d_in, const int* in_sizes, int n_in,
                              void* d_out, int out_size)
{
    (void)in_sizes; (void)n_in; (void)out_size;
    const float* x  = (const float*)d_in[0];
    const float* Tr = (const float*)d_in[1];
    const float* Ti = (const float*)d_in[2];
    const float* wr = (const float*)d_in[3];
    const float* wi = (const float*)d_in[4];
    const float* b  = (const float*)d_in[5];
    float* out = (float*)d_out;

    cudaFuncSetAttribute(bessel_conv_kernel,
                         cudaFuncAttributeMaxDynamicSharedMemorySize, SMEM_BYTES);

    dim3 grid(WW / TLW, HH / TLH, 32);   /* (4,4,32) = 512 CTAs */
    bessel_conv_kernel<<<grid, NTHREADS, SMEM_BYTES>>>(x, Tr, Ti, wr, wi, b, out);
}

// round 15
// speedup vs baseline: 1.6923x; 1.1309x over previous
#include <cuda_runtime.h>

typedef unsigned long long u64;
typedef unsigned int u32;

#define KK    81
#define MM    16
#define JJ    8
#define CINN  64
#define COUTN 64
#define HH    64
#define WW    64
#define TLW   16
#define TLH   16
#define XCOLS 24
#define XPIX  576
#define NCP   32
#define NTHREADS 256

/* smem layout (bytes) */
#define SM_TB   147456            /* x tile: 32cp*576*8B before this        */
#define TB_LO   1216              /* u32 index offset of lo plane (16n*76)  */
#define SM_U    157184            /* Tb: 2*16*76*4 = 9728B                  */
#define U_PITCH 36
#define U_VAR   (256 * U_PITCH)   /* 9216B * 4 variants                     */
#define SM_W    (SM_U + 4 * U_VAR)        /* 194048 */
#define W_PITCH 36
#define W_VAR   (64 * W_PITCH)    /* 2304B * 6 variants                     */
#define SMEM_BYTES (SM_W + 6 * W_VAR)     /* 207872 */

/* bf16x2 pack: low 16 = lo arg, high 16 = hi arg */
__device__ __forceinline__ u32 bf2(float lo, float hi) {
    u32 r; asm("cvt.rn.bf16x2.f32 %0, %1, %2;" : "=r"(r) : "f"(hi), "f"(lo)); return r;
}
__device__ __forceinline__ float bflo(u32 w) { return __uint_as_float(w << 16); }
__device__ __forceinline__ float bfhi(u32 w) { return __uint_as_float(w & 0xffff0000u); }

__device__ __forceinline__ void mma16816(float* d, const u32* a, const u32* b) {
    asm("mma.sync.aligned.m16n8k16.row.col.f32.bf16.bf16.f32 "
        "{%0,%1,%2,%3}, {%4,%5,%6,%7}, {%8,%9}, {%0,%1,%2,%3};"
        : "+f"(d[0]), "+f"(d[1]), "+f"(d[2]), "+f"(d[3])
        : "r"(a[0]), "r"(a[1]), "r"(a[2]), "r"(a[3]), "r"(b[0]), "r"(b[1]));
}

extern __shared__ char smem_raw[];

__global__ void __launch_bounds__(NTHREADS, 1)
bessel_conv_kernel(const float* __restrict__ x,
                   const float* __restrict__ T_real,
                   const float* __restrict__ T_imag,
                   const float* __restrict__ w_r,
                   const float* __restrict__ w_i,
                   const float* __restrict__ bias,
                   float* __restrict__ out)
{
    float2* xs2 = (float2*)smem_raw;                 /* [32 cp][576 px] */

    const int tid  = threadIdx.x;
    const int lane = tid & 31;
    const int wid  = tid >> 5;
    const int tileX = blockIdx.x, tileY = blockIdx.y, b = blockIdx.z;
    const int r4 = lane >> 2, t4 = lane & 3;

    /* W staging role: word wid covers (cin wc, j-pair (wj, wj+4)) */
    const int wc  = wid >> 2;
    const int wj  = wid & 3;
    const int wn2 = lane * 2;

    /* ---- stage x tile (+4 halo, zero padded), cin-paired float2 ---- */
    {
        const int baseY = tileY * TLH - 4, baseX = tileX * TLW - 4;
        const float* xb = x + (size_t)b * CINN * HH * WW;
        for (int idx = tid; idx < NCP * XPIX; idx += NTHREADS) {
            int cp = idx / XPIX, rem = idx - cp * XPIX;
            int r = rem / XCOLS, c = rem - r * XCOLS;
            int iy = baseY + r, ix = baseX + c;
            float2 v = make_float2(0.f, 0.f);
            if (iy >= 0 && iy < HH && ix >= 0 && ix < WW) {
                const float* pb = xb + ((size_t)(2 * cp) * HH + iy) * WW + ix;
                v.x = pb[0]; v.y = pb[(size_t)HH * WW];
            }
            xs2[idx] = v;
        }
    }

    /* Stage B product tables: A var {0:Urh,1:Url,2:Uih,3:Uil},
       W var {0:Wrh,1:Wrl,2:Wih,3:Wil,4:-Wih,5:-Wil} */
    const int PA[6]  = {0, 1, 0, 2, 3, 2};
    const int PBR[6] = {0, 0, 1, 4, 4, 5};
    const int PBI[6] = {2, 2, 3, 0, 0, 1};

#pragma unroll 1
    for (int m = 0; m < MM; ++m) {
        __syncthreads();             /* prior m's Tb readers done; x visible */

        /* ---- stage Tb: B[K=144, N=16], n = 2j+ri, k = k1*16+k2 (k2>8 -> 0)
               packed k-pair words: kw = k1*8+w covers k2 = 2w, 2w+1
               layout u32[(var*16 + n)*76 + kw]                            ---- */
        {
            const float* Trm = T_real + m * KK * JJ;
            const float* Tim = T_imag + m * KK * JJ;
            u32* tb = (u32*)(smem_raw + SM_TB);
            for (int idx = tid; idx < 16 * 72; idx += NTHREADS) {
                int n  = idx / 72;
                int kw = idx - n * 72;
                int k1 = kw >> 3, w = kw & 7;
                int k2 = 2 * w;
                int j  = n >> 1;
                const float* src = (n & 1) ? Tim : Trm;
                float v0 = (k2 <= 8) ? src[(k1 * 9 + k2) * 8 + j] : 0.f;
                float v1 = (k2 < 8)  ? src[(k1 * 9 + k2 + 1) * 8 + j] : 0.f;
                u32 hi = bf2(v0, v1);
                u32 lo = bf2(v0 - bflo(hi), v1 - bfhi(hi));
                tb[n * 76 + kw]         = hi;
                tb[TB_LO + n * 76 + kw] = lo;
            }
        }
        __syncthreads();

        float Dk[2][8][2][4];        /* Stage B acc: [mtile][ntile][re/im][4] */
#pragma unroll
        for (int a = 0; a < 2; ++a)
#pragma unroll
            for (int n = 0; n < 8; ++n)
#pragma unroll
                for (int e = 0; e < 2; ++e)
#pragma unroll
                    for (int q = 0; q < 4; ++q) Dk[a][n][e][q] = 0.f;

#pragma unroll 1
        for (int cp = 0; cp < NCP; ++cp) {
            /* ---- W prefetch (j-pair = wj, wj+4) ---- */
            const float* wrp = w_r + (((size_t)m * JJ + wj) * CINN + (2 * cp + wc)) * COUTN + wn2;
            const float* wip = w_i + (((size_t)m * JJ + wj) * CINN + (2 * cp + wc)) * COUTN + wn2;
            float2 pr0 = __ldg((const float2*)wrp);
            float2 pr1 = __ldg((const float2*)(wrp + 4 * CINN * COUTN));
            float2 pi0 = __ldg((const float2*)wip);
            float2 pi1 = __ldg((const float2*)(wip + 4 * CINN * COUTN));

            /* ---- Stage A on tensor: AD[cin][mt][nt][4] = im2col(x) . Tb ---- */
            float AD[2][2][2][4];
#pragma unroll
            for (int c = 0; c < 2; ++c)
#pragma unroll
                for (int a = 0; a < 2; ++a)
#pragma unroll
                    for (int n = 0; n < 2; ++n)
#pragma unroll
                        for (int q = 0; q < 4; ++q) AD[c][a][n][q] = 0.f;

            const float2* xpl = xs2 + cp * XPIX;
            const u32* tbp = (const u32*)(smem_raw + SM_TB);

#pragma unroll 3
            for (int ks = 0; ks < 9; ++ks) {
                u32 bh[2][2], bl[2][2];
#pragma unroll
                for (int nt = 0; nt < 2; ++nt) {
                    int ni = (r4 + 8 * nt) * 76 + ks * 8 + t4;
                    bh[nt][0] = tbp[ni];          bh[nt][1] = tbp[ni + 4];
                    bl[nt][0] = tbp[TB_LO + ni];  bl[nt][1] = tbp[TB_LO + ni + 4];
                }
#pragma unroll
                for (int mt = 0; mt < 2; ++mt) {
                    const float2* xr = xpl + (wid * 2 + mt + ks) * XCOLS + r4 + 2 * t4;
                    float2 v0 = xr[0],  v1 = xr[1];
                    float2 v2 = xr[8],  v3 = xr[9];
                    float2 v4 = xr[16], v5 = xr[17];
                    u32 Ah[2][4], Al[2][4];
                    Ah[0][0] = bf2(v0.x, v1.x);
                    Ah[0][1] = bf2(v2.x, v3.x);
                    Ah[0][2] = Ah[0][1];
                    Ah[0][3] = bf2(v4.x, v5.x);
                    Al[0][0] = bf2(v0.x - bflo(Ah[0][0]), v1.x - bfhi(Ah[0][0]));
                    Al[0][1] = bf2(v2.x - bflo(Ah[0][1]), v3.x - bfhi(Ah[0][1]));
                    Al[0][2] = Al[0][1];
                    Al[0][3] = bf2(v4.x - bflo(Ah[0][3]), v5.x - bfhi(Ah[0][3]));
                    Ah[1][0] = bf2(v0.y, v1.y);
                    Ah[1][1] = bf2(v2.y, v3.y);
                    Ah[1][2] = Ah[1][1];
                    Ah[1][3] = bf2(v4.y, v5.y);
                    Al[1][0] = bf2(v0.y - bflo(Ah[1][0]), v1.y - bfhi(Ah[1][0]));
                    Al[1][1] = bf2(v2.y - bflo(Ah[1][1]), v3.y - bfhi(Ah[1][1]));
                    Al[1][2] = Al[1][1];
                    Al[1][3] = bf2(v4.y - bflo(Ah[1][3]), v5.y - bfhi(Ah[1][3]));
#pragma unroll
                    for (int c = 0; c < 2; ++c)
#pragma unroll
                        for (int nt = 0; nt < 2; ++nt) {
                            mma16816(AD[c][mt][nt], Ah[c], bh[nt]);
                            mma16816(AD[c][mt][nt], Al[c], bh[nt]);
                            mma16816(AD[c][mt][nt], Ah[c], bl[nt]);
                        }
                }
            }

            __syncthreads();   /* previous Stage B's U/W reads done */

            /* ---- U -> smem planes (word t4 = j-pair (t4, t4+4)) ---- */
#pragma unroll
            for (int c = 0; c < 2; ++c)
#pragma unroll
                for (int mt = 0; mt < 2; ++mt) {
                    int p = wid * 32 + mt * 16 + r4;
                    char* ub = smem_raw + SM_U + p * U_PITCH + (c * 4 + t4) * 4;
                    {
                        float e0 = AD[c][mt][0][0], e1 = AD[c][mt][1][0];
                        u32 rh = bf2(e0, e1);
                        u32 rl = bf2(e0 - bflo(rh), e1 - bfhi(rh));
                        float f0 = AD[c][mt][0][1], f1 = AD[c][mt][1][1];
                        u32 ih = bf2(f0, f1);
                        u32 il = bf2(f0 - bflo(ih), f1 - bfhi(ih));
                        *(u32*)(ub)             = rh;
                        *(u32*)(ub + U_VAR)     = rl;
                        *(u32*)(ub + 2 * U_VAR) = ih;
                        *(u32*)(ub + 3 * U_VAR) = il;
                    }
                    {
                        char* ub2 = ub + 8 * U_PITCH;
                        float e0 = AD[c][mt][0][2], e1 = AD[c][mt][1][2];
                        u32 rh = bf2(e0, e1);
                        u32 rl = bf2(e0 - bflo(rh), e1 - bfhi(rh));
                        float f0 = AD[c][mt][0][3], f1 = AD[c][mt][1][3];
                        u32 ih = bf2(f0, f1);
                        u32 il = bf2(f0 - bflo(ih), f1 - bfhi(ih));
                        *(u32*)(ub2)             = rh;
                        *(u32*)(ub2 + U_VAR)     = rl;
                        *(u32*)(ub2 + 2 * U_VAR) = ih;
                        *(u32*)(ub2 + 3 * U_VAR) = il;
                    }
                }

            /* ---- W -> smem variants (row = cout, word wid) ---- */
#pragma unroll
            for (int s = 0; s < 2; ++s) {
                float vr0 = s ? pr0.y : pr0.x;   /* j = wj   (k even) */
                float vr1 = s ? pr1.y : pr1.x;   /* j = wj+4 (k odd)  */
                float vi0 = s ? pi0.y : pi0.x;
                float vi1 = s ? pi1.y : pi1.x;
                u32 hR = bf2(vr0, vr1);
                u32 lR = bf2(vr0 - bflo(hR), vr1 - bfhi(hR));
                u32 hI = bf2(vi0, vi1);
                u32 lI = bf2(vi0 - bflo(hI), vi1 - bfhi(hI));
                char* wb = smem_raw + SM_W + (wn2 + s) * W_PITCH + wid * 4;
                *(u32*)(wb)             = hR;
                *(u32*)(wb + W_VAR)     = lR;
                *(u32*)(wb + 2 * W_VAR) = hI;
                *(u32*)(wb + 3 * W_VAR) = lI;
                *(u32*)(wb + 4 * W_VAR) = hI ^ 0x80008000u;
                *(u32*)(wb + 5 * W_VAR) = lI ^ 0x80008000u;
            }
            __syncthreads();   /* U + W visible */

            /* ---- Stage B (proven round-14 code) ---- */
            u32 afr[2][4][4];
#pragma unroll
            for (int mt = 0; mt < 2; ++mt) {
                const int row = wid * 32 + mt * 16 + r4;
#pragma unroll
                for (int v = 0; v < 4; ++v) {
                    const char* uv = smem_raw + SM_U + v * U_VAR;
                    afr[mt][v][0] = *(const u32*)(uv + row * U_PITCH + t4 * 4);
                    afr[mt][v][1] = *(const u32*)(uv + (row + 8) * U_PITCH + t4 * 4);
                    afr[mt][v][2] = *(const u32*)(uv + row * U_PITCH + 16 + t4 * 4);
                    afr[mt][v][3] = *(const u32*)(uv + (row + 8) * U_PITCH + 16 + t4 * 4);
                }
            }
#pragma unroll
            for (int nt = 0; nt < 8; ++nt) {
                u32 bfr[6][2];
                const int rowb = nt * 8 + r4;
#pragma unroll
                for (int v = 0; v < 6; ++v) {
                    const char* wv = smem_raw + SM_W + v * W_VAR;
                    bfr[v][0] = *(const u32*)(wv + rowb * W_PITCH + t4 * 4);
                    bfr[v][1] = *(const u32*)(wv + rowb * W_PITCH + 16 + t4 * 4);
                }
#pragma unroll
                for (int mt = 0; mt < 2; ++mt) {
#pragma unroll
                    for (int pi = 0; pi < 6; ++pi)
                        mma16816(Dk[mt][nt][0], afr[mt][PA[pi]], bfr[PBR[pi]]);
#pragma unroll
                    for (int pi = 0; pi < 6; ++pi)
                        mma16816(Dk[mt][nt][1], afr[mt][PA[pi]], bfr[PBI[pi]]);
                }
            }
        }

        /* ---- epilogue: |y|^2 RMW into out (m=0 initializes + bias) ---- */
#pragma unroll
        for (int mt = 0; mt < 2; ++mt) {
#pragma unroll
            for (int nt = 0; nt < 8; ++nt) {
                const float* dR = Dk[mt][nt][0];
                const float* dI = Dk[mt][nt][1];
                const int p0 = wid * 32 + mt * 16 + r4;
                const int p1 = p0 + 8;
                const int c0 = nt * 8 + t4 * 2;
                float v00 = dR[0] * dR[0] + dI[0] * dI[0];
                float v01 = dR[1] * dR[1] + dI[1] * dI[1];
                float v10 = dR[2] * dR[2] + dI[2] * dI[2];
                float v11 = dR[3] * dR[3] + dI[3] * dI[3];
                float* o00 = out + ((size_t)b * COUTN + c0) * (HH * WW)
                           + (tileY * TLH + (p0 >> 4)) * WW + tileX * TLW + (p0 & 15);
                float* o10 = out + ((size_t)b * COUTN + c0) * (HH * WW)
                           + (tileY * TLH + (p1 >> 4)) * WW + tileX * TLW + (p1 & 15);
                if (m == 0) {
                    float b0 = __ldg(bias + c0), b1 = __ldg(bias + c0 + 1);
                    o00[0]       = v00 + b0;
                    o00[HH * WW] = v01 + b1;
                    o10[0]       = v10 + b0;
                    o10[HH * WW] = v11 + b1;
                } else {
                    o00[0]       += v00;
                    o00[HH * WW] += v01;
                    o10[0]       += v10;
                    o10[HH * WW] += v11;
                }
            }
        }
    }
}

extern "C" void kernel_launch(void* const* d_in, const int* in_sizes, int n_in,
                              void* d_out, int out_size)
{
    (void)in_sizes; (void)n_in; (void)out_size;
    const float* x  = (const float*)d_in[0];
    const float* Tr = (const float*)d_in[1];
    const float* Ti = (const float*)d_in[2];
    const float* wr = (const float*)d_in[3];
    const float* wi = (const float*)d_in[4];
    const float* b  = (const float*)d_in[5];
    float* out = (float*)d_out;

    cudaFuncSetAttribute(bessel_conv_kernel,
                         cudaFuncAttributeMaxDynamicSharedMemorySize, SMEM_BYTES);

    dim3 grid(WW / TLW, HH / TLH, 32);   /* (4,4,32) = 512 CTAs */
    bessel_conv_kernel<<<grid, NTHREADS, SMEM_BYTES>>>(x, Tr, Ti, wr, wi, b, out);
}

// round 16
// speedup vs baseline: 1.9119x; 1.1298x over previous
#include <cuda_runtime.h>

typedef unsigned long long u64;
typedef unsigned int u32;

#define MM    16
#define JJ    8
#define CINN  64
#define COUTN 64
#define HH    64
#define WW    64
#define TLW   16
#define TLH   16
#define XCOLS 24
#define XPIX  576
#define NCP   32
#define NTHREADS 512

/* smem layout (bytes) */
#define TBP     52                 /* Tb row pitch in u32 words (48 + pad)  */
#define TBLO    (16 * TBP)         /* u32 offset of lo plane                */
#define SM_TB   147456             /* x tile: 32cp*576*8B before this       */
#define SM_U    (SM_TB + 2 * 16 * TBP * 4)     /* 154112 */
#define U_PITCH 36
#define U_VAR   (256 * U_PITCH)    /* 9216B * 4 variants                    */
#define SM_W    (SM_U + 4 * U_VAR)             /* 190976 */
#define W_PITCH 36
#define W_VAR   (64 * W_PITCH)     /* 2304B * 6 variants                    */
#define SMEM_BYTES (SM_W + 6 * W_VAR)          /* 204800 */

/* bf16x2 pack: low 16 = first arg, high 16 = second arg */
__device__ __forceinline__ u32 bf2(float lo, float hi) {
    u32 r; asm("cvt.rn.bf16x2.f32 %0, %1, %2;" : "=r"(r) : "f"(hi), "f"(lo)); return r;
}
__device__ __forceinline__ float bflo(u32 w) { return __uint_as_float(w << 16); }
__device__ __forceinline__ float bfhi(u32 w) { return __uint_as_float(w & 0xffff0000u); }

__device__ __forceinline__ void mma16816(float* d, const u32* a, const u32* b) {
    asm("mma.sync.aligned.m16n8k16.row.col.f32.bf16.bf16.f32 "
        "{%0,%1,%2,%3}, {%4,%5,%6,%7}, {%8,%9}, {%0,%1,%2,%3};"
        : "+f"(d[0]), "+f"(d[1]), "+f"(d[2]), "+f"(d[3])
        : "r"(a[0]), "r"(a[1]), "r"(a[2]), "r"(a[3]), "r"(b[0]), "r"(b[1]));
}

extern __shared__ char smem_raw[];

__global__ void __launch_bounds__(NTHREADS, 1)
bessel_conv_kernel(const float* __restrict__ x,
                   const float* __restrict__ T_real,
                   const float* __restrict__ T_imag,
                   const float* __restrict__ w_r,
                   const float* __restrict__ w_i,
                   const float* __restrict__ bias,
                   float* __restrict__ out)
{
    float2* xs2 = (float2*)smem_raw;                 /* [32 cp][576 px] */
    u32*    tb  = (u32*)(smem_raw + SM_TB);

    const int tid  = threadIdx.x;
    const int lane = tid & 31;
    const int wid  = tid >> 5;           /* 0..15: warp owns pixel row wid  */
    const int r4 = lane >> 2, t4 = lane & 3;
    const int tileX = blockIdx.x, tileY = blockIdx.y, b = blockIdx.z;

    /* W staging role: (ri, cin, j) = wid bits */
    const int ri  = wid >> 3;
    const int wc  = (wid >> 2) & 1;
    const int wj  = wid & 3;
    const int wn2 = lane * 2;

    /* ---- stage x tile (+4 halo, zero padded), cin-paired float2 ---- */
    {
        const int baseY = tileY * TLH - 4, baseX = tileX * TLW - 4;
        const float* xb = x + (size_t)b * CINN * HH * WW;
        for (int idx = tid; idx < NCP * XPIX; idx += NTHREADS) {
            int cp = idx / XPIX, rem = idx - cp * XPIX;
            int r = rem / XCOLS, c = rem - r * XCOLS;
            int iy = baseY + r, ix = baseX + c;
            float2 v = make_float2(0.f, 0.f);
            if (iy >= 0 && iy < HH && ix >= 0 && ix < WW) {
                const float* pb = xb + ((size_t)(2 * cp) * HH + iy) * WW + ix;
                v.x = pb[0]; v.y = pb[(size_t)HH * WW];
            }
            xs2[idx] = v;
        }
    }

    const int PA[6]  = {0, 1, 0, 2, 3, 2};
    const int PBR[6] = {0, 0, 1, 4, 4, 5};
    const int PBI[6] = {2, 2, 3, 0, 0, 1};

#pragma unroll 1
    for (int m = 0; m < MM; ++m) {
        /* ---- stage Tb (K=96 packing): chunks 0-4 = two k1-rows (k2 0..7),
               chunk 5 = k2==8 column. n = 2j+ri. word tw covers l=2tw,2tw+1 ---- */
        {
            const float* Trm = T_real + m * 648;
            const float* Tim = T_imag + m * 648;
            for (int idx = tid; idx < 16 * 48; idx += NTHREADS) {
                int n = idx / 48, w = idx - n * 48;
                int a = w >> 3, tw = w & 7;
                int j = n >> 1;
                const float* src = (n & 1) ? Tim : Trm;
                int l0 = 2 * tw, l1 = l0 + 1;
                float v0, v1;
                if (a < 5) {
                    int k1a = 2 * a + (l0 >> 3), k2a = l0 & 7;
                    int k1b = 2 * a + (l1 >> 3), k2b = l1 & 7;
                    v0 = (k1a <= 8) ? src[(k1a * 9 + k2a) * 8 + j] : 0.f;
                    v1 = (k1b <= 8) ? src[(k1b * 9 + k2b) * 8 + j] : 0.f;
                } else {
                    v0 = (l0 <= 8) ? src[(l0 * 9 + 8) * 8 + j] : 0.f;
                    v1 = (l1 <= 8) ? src[(l1 * 9 + 8) * 8 + j] : 0.f;
                }
                u32 hi = bf2(v0, v1);
                u32 lo = bf2(v0 - bflo(hi), v1 - bfhi(hi));
                tb[n * TBP + w]        = hi;
                tb[TBLO + n * TBP + w] = lo;
            }
        }
        __syncthreads();   /* Tb (and x at m=0) visible; prev m fully drained */

        float Dk[8][2][4];               /* [ntile][re/im][frag] : 64 regs */
#pragma unroll
        for (int n = 0; n < 8; ++n)
#pragma unroll
            for (int e = 0; e < 2; ++e)
#pragma unroll
                for (int q = 0; q < 4; ++q) Dk[n][e][q] = 0.f;

#pragma unroll 1
        for (int cp = 0; cp < NCP; ++cp) {
            /* ---- W prefetch: this warp's (ri, cin wc, j wj / wj+4) ---- */
            const float* wsrc = (ri ? w_i : w_r)
                + (((size_t)m * JJ + wj) * CINN + (2 * cp + wc)) * COUTN + wn2;
            float2 pj0 = __ldg((const float2*)wsrc);
            float2 pj4 = __ldg((const float2*)(wsrc + 4 * CINN * COUTN));

            /* ---- Stage A: AD[cin][nt][4], K=96 in 6 chunks ---- */
            float AD[2][2][4];
#pragma unroll
            for (int c = 0; c < 2; ++c)
#pragma unroll
                for (int n = 0; n < 2; ++n)
#pragma unroll
                    for (int q = 0; q < 4; ++q) AD[c][n][q] = 0.f;

            const float2* xt = xs2 + cp * XPIX;
            const int colA = r4 + 2 * t4;

#pragma unroll
            for (int a = 0; a < 5; ++a) {
                u32 bh[2][2], bl[2][2];
#pragma unroll
                for (int nt = 0; nt < 2; ++nt) {
                    int ni = (r4 + 8 * nt) * TBP + a * 8 + t4;
                    bh[nt][0] = tb[ni];        bh[nt][1] = tb[ni + 4];
                    bl[nt][0] = tb[TBLO + ni]; bl[nt][1] = tb[TBLO + ni + 4];
                }
                const float2* x0 = xt + (wid + 2 * a) * XCOLS + colA;
                u32 Ah[2][4], Al[2][4];
                {
                    float2 v0 = x0[0], v1 = x0[1], v2 = x0[8], v3 = x0[9];
#pragma unroll
                    for (int c = 0; c < 2; ++c) {
                        float e0 = c ? v0.y : v0.x, e1 = c ? v1.y : v1.x;
                        float e2 = c ? v2.y : v2.x, e3 = c ? v3.y : v3.x;
                        Ah[c][0] = bf2(e0, e1);
                        Al[c][0] = bf2(e0 - bflo(Ah[c][0]), e1 - bfhi(Ah[c][0]));
                        Ah[c][1] = bf2(e2, e3);
                        Al[c][1] = bf2(e2 - bflo(Ah[c][1]), e3 - bfhi(Ah[c][1]));
                    }
                }
                if (a < 4) {
                    const float2* x1 = x0 + XCOLS;
                    float2 v0 = x1[0], v1 = x1[1], v2 = x1[8], v3 = x1[9];
#pragma unroll
                    for (int c = 0; c < 2; ++c) {
                        float e0 = c ? v0.y : v0.x, e1 = c ? v1.y : v1.x;
                        float e2 = c ? v2.y : v2.x, e3 = c ? v3.y : v3.x;
                        Ah[c][2] = bf2(e0, e1);
                        Al[c][2] = bf2(e0 - bflo(Ah[c][2]), e1 - bfhi(Ah[c][2]));
                        Ah[c][3] = bf2(e2, e3);
                        Al[c][3] = bf2(e2 - bflo(Ah[c][3]), e3 - bfhi(Ah[c][3]));
                    }
                } else {   /* k1 = 9 rows are pad: explicit zeros (no OOB reads) */
#pragma unroll
                    for (int c = 0; c < 2; ++c) {
                        Ah[c][2] = Ah[c][3] = 0u;
                        Al[c][2] = Al[c][3] = 0u;
                    }
                }
#pragma unroll
                for (int c = 0; c < 2; ++c)
#pragma unroll
                    for (int nt = 0; nt < 2; ++nt) {
                        mma16816(AD[c][nt], Ah[c], bh[nt]);
                        mma16816(AD[c][nt], Al[c], bh[nt]);
                        mma16816(AD[c][nt], Ah[c], bl[nt]);
                    }
            }
            /* ---- chunk 5: k2 == 8 column (l = k1) ---- */
            {
                u32 bh[2][2], bl[2][2];
#pragma unroll
                for (int nt = 0; nt < 2; ++nt) {
                    int ni = (r4 + 8 * nt) * TBP + 5 * 8 + t4;
                    bh[nt][0] = tb[ni];        bh[nt][1] = tb[ni + 4];
                    bl[nt][0] = tb[TBLO + ni]; bl[nt][1] = tb[TBLO + ni + 4];
                }
                float2 va = xt[(wid + 2 * t4) * XCOLS + r4 + 8];
                float2 vb = xt[(wid + 2 * t4 + 1) * XCOLS + r4 + 8];
                float2 vc = xt[(wid + 2 * t4) * XCOLS + r4 + 16];
                float2 vd = xt[(wid + 2 * t4 + 1) * XCOLS + r4 + 16];
                float2 ve = make_float2(0.f, 0.f), vf = make_float2(0.f, 0.f);
                if (t4 == 0) {
                    ve = xt[(wid + 8) * XCOLS + r4 + 8];
                    vf = xt[(wid + 8) * XCOLS + r4 + 16];
                }
                u32 Ah[2][4], Al[2][4];
#pragma unroll
                for (int c = 0; c < 2; ++c) {
                    float ea = c ? va.y : va.x, eb = c ? vb.y : vb.x;
                    float ec = c ? vc.y : vc.x, ed = c ? vd.y : vd.x;
                    float ee = c ? ve.y : ve.x, ef = c ? vf.y : vf.x;
                    Ah[c][0] = bf2(ea, eb);
                    Al[c][0] = bf2(ea - bflo(Ah[c][0]), eb - bfhi(Ah[c][0]));
                    Ah[c][1] = bf2(ec, ed);
                    Al[c][1] = bf2(ec - bflo(Ah[c][1]), ed - bfhi(Ah[c][1]));
                    Ah[c][2] = bf2(ee, 0.f);
                    Al[c][2] = bf2(ee - bflo(Ah[c][2]), 0.f);
                    Ah[c][3] = bf2(ef, 0.f);
                    Al[c][3] = bf2(ef - bflo(Ah[c][3]), 0.f);
                }
#pragma unroll
                for (int c = 0; c < 2; ++c)
#pragma unroll
                    for (int nt = 0; nt < 2; ++nt) {
                        mma16816(AD[c][nt], Ah[c], bh[nt]);
                        mma16816(AD[c][nt], Al[c], bh[nt]);
                        mma16816(AD[c][nt], Ah[c], bl[nt]);
                    }
            }

            __syncthreads();   /* previous Stage B's U/W reads done */

            /* ---- U -> smem planes (word c*4+t4 = j-pair (t4, t4+4)) ---- */
#pragma unroll
            for (int c = 0; c < 2; ++c) {
                char* ub = smem_raw + SM_U + (wid * 16 + r4) * U_PITCH + (c * 4 + t4) * 4;
                u32 hR = bf2(AD[c][0][0], AD[c][1][0]);
                u32 lR = bf2(AD[c][0][0] - bflo(hR), AD[c][1][0] - bfhi(hR));
                u32 hI = bf2(AD[c][0][1], AD[c][1][1]);
                u32 lI = bf2(AD[c][0][1] - bflo(hI), AD[c][1][1] - bfhi(hI));
                *(u32*)(ub)             = hR;
                *(u32*)(ub + U_VAR)     = lR;
                *(u32*)(ub + 2 * U_VAR) = hI;
                *(u32*)(ub + 3 * U_VAR) = lI;
                char* ub2 = ub + 8 * U_PITCH;
                hR = bf2(AD[c][0][2], AD[c][1][2]);
                lR = bf2(AD[c][0][2] - bflo(hR), AD[c][1][2] - bfhi(hR));
                hI = bf2(AD[c][0][3], AD[c][1][3]);
                lI = bf2(AD[c][0][3] - bflo(hI), AD[c][1][3] - bfhi(hI));
                *(u32*)(ub2)             = hR;
                *(u32*)(ub2 + U_VAR)     = lR;
                *(u32*)(ub2 + 2 * U_VAR) = hI;
                *(u32*)(ub2 + 3 * U_VAR) = lI;
            }

            /* ---- W -> smem variants (row = cout, word wc*4+wj) ---- */
#pragma unroll
            for (int s = 0; s < 2; ++s) {
                float v0 = s ? pj0.y : pj0.x;    /* j = wj   */
                float v1 = s ? pj4.y : pj4.x;    /* j = wj+4 */
                u32 hi = bf2(v0, v1);
                u32 lo = bf2(v0 - bflo(hi), v1 - bfhi(hi));
                char* wp = smem_raw + SM_W + (wn2 + s) * W_PITCH + (wc * 4 + wj) * 4;
                if (ri == 0) {
                    *(u32*)(wp)         = hi;
                    *(u32*)(wp + W_VAR) = lo;
                } else {
                    *(u32*)(wp + 2 * W_VAR) = hi;
                    *(u32*)(wp + 3 * W_VAR) = lo;
                    *(u32*)(wp + 4 * W_VAR) = hi ^ 0x80008000u;
                    *(u32*)(wp + 5 * W_VAR) = lo ^ 0x80008000u;
                }
            }
            __syncthreads();   /* U + W visible */

            /* ---- Stage B (round-14 verified structure, 1 mtile) ---- */
            u32 afr[4][4];
            const int rowA = wid * 16 + r4;
#pragma unroll
            for (int v = 0; v < 4; ++v) {
                const char* uv = smem_raw + SM_U + v * U_VAR;
                afr[v][0] = *(const u32*)(uv + rowA * U_PITCH + t4 * 4);
                afr[v][1] = *(const u32*)(uv + (rowA + 8) * U_PITCH + t4 * 4);
                afr[v][2] = *(const u32*)(uv + rowA * U_PITCH + 16 + t4 * 4);
                afr[v][3] = *(const u32*)(uv + (rowA + 8) * U_PITCH + 16 + t4 * 4);
            }
#pragma unroll
            for (int nt = 0; nt < 8; ++nt) {
                u32 bfr[6][2];
                const int rowb = nt * 8 + r4;
#pragma unroll
                for (int v = 0; v < 6; ++v) {
                    const char* wv = smem_raw + SM_W + v * W_VAR;
                    bfr[v][0] = *(const u32*)(wv + rowb * W_PITCH + t4 * 4);
                    bfr[v][1] = *(const u32*)(wv + rowb * W_PITCH + 16 + t4 * 4);
                }
#pragma unroll
                for (int pi = 0; pi < 6; ++pi)
                    mma16816(Dk[nt][0], afr[PA[pi]], bfr[PBR[pi]]);
#pragma unroll
                for (int pi = 0; pi < 6; ++pi)
                    mma16816(Dk[nt][1], afr[PA[pi]], bfr[PBI[pi]]);
            }
        }

        /* ---- epilogue: |y|^2 RMW into out (m=0 initializes + bias) ---- */
#pragma unroll
        for (int nt = 0; nt < 8; ++nt) {
            const float* dR = Dk[nt][0];
            const float* dI = Dk[nt][1];
            const int c0 = nt * 8 + t4 * 2;
            float v00 = dR[0] * dR[0] + dI[0] * dI[0];
            float v01 = dR[1] * dR[1] + dI[1] * dI[1];
            float v10 = dR[2] * dR[2] + dI[2] * dI[2];
            float v11 = dR[3] * dR[3] + dI[3] * dI[3];
            float* ob = out + ((size_t)b * COUTN + c0) * (HH * WW)
                      + (tileY * TLH + wid) * WW + tileX * TLW;
            if (m == 0) {
                float b0 = __ldg(bias + c0), b1 = __ldg(bias + c0 + 1);
                ob[r4]                 = v00 + b0;
                ob[HH * WW + r4]       = v01 + b1;
                ob[r4 + 8]             = v10 + b0;
                ob[HH * WW + r4 + 8]   = v11 + b1;
            } else {
                ob[r4]               += v00;
                ob[HH * WW + r4]     += v01;
                ob[r4 + 8]           += v10;
                ob[HH * WW + r4 + 8] += v11;
            }
        }
    }
}

extern "C" void kernel_launch(void* const* d_in, const int* in_sizes, int n_in,
                              void* d_out, int out_size)
{
    (void)in_sizes; (void)n_in; (void)out_size;
    const float* x  = (const float*)d_in[0];
    const float* Tr = (const float*)d_in[1];
    const float* Ti = (const float*)d_in[2];
    const float* wr = (const float*)d_in[3];
    const float* wi = (const float*)d_in[4];
    const float* b  = (const float*)d_in[5];
    float* out = (float*)d_out;

    cudaFuncSetAttribute(bessel_conv_kernel,
                         cudaFuncAttributeMaxDynamicSharedMemorySize, SMEM_BYTES);

    dim3 grid(WW / TLW, HH / TLH, 32);   /* (4,4,32) = 512 CTAs */
    bessel_conv_kernel<<<grid, NTHREADS, SMEM_BYTES>>>(x, Tr, Ti, wr, wi, b, out);
}